// round 9
// baseline (speedup 1.0000x reference)
#include <cuda_runtime.h>

#define HH 224
#define WW 224
#define HW (HH * WW)
#define BB 256
#define NTOT (BB * HW)
#define DTc 0.15f
#define PIf 3.14159265358979f

#define TY 38                  // interior rows per tile
#define HALO 5                 // 5 fused steps per kernel
#define RR (TY + 2 * HALO)     // 48 data rows
#define RPAIRS (RR / 2)        // 24 vertical row-pair packs
#define RPP (RPAIRS + 2)       // +2 zero-pad pack rows -> 26
#define TCOLS 112              // thread-columns (each owns 2 pixel cols)
#define PW2 114                // plane width incl pads
#define RS (2 * PW2)           // row stride: E plane then O plane (228 cells)
#define TILES 6                // 6*38 = 228 >= 224
#define STRIPS 4
#define NTHREADS (TCOLS * STRIPS)    // 448; 2 CTAs/SM
#define PACKS_PER (RPAIRS / STRIPS)  // 6 packs per thread -> 48 state regs
#define SMP (RPP * RS)               // cells per buffer = 5928
#define SMEM_BYTES (2 * SMP * 8)     // 94848 B -> 2 CTAs/SM easily

typedef unsigned long long u64;
typedef unsigned int u32;

__device__ float g_s[NTOT];
__device__ float g_c[NTOT];
__device__ int g_flag;          // omega-nonzero flag (recomputed every launch)

// ---- packed f32x2 helpers ----
__device__ __forceinline__ u64 pk2(float lo, float hi) {
    u64 r; asm("mov.b64 %0, {%1, %2};" : "=l"(r) : "f"(lo), "f"(hi)); return r;
}
__device__ __forceinline__ void unpk2(u64 v, float& lo, float& hi) {
    asm("mov.b64 {%0, %1}, %2;" : "=f"(lo), "=f"(hi) : "l"(v));
}
// (a.hi, b.lo)
__device__ __forceinline__ u64 funnel(u64 a, u64 b) {
    u64 r;
    asm("{\n\t.reg .f32 al, ah, bl, bh;\n\t"
        "mov.b64 {al, ah}, %1;\n\t"
        "mov.b64 {bl, bh}, %2;\n\t"
        "mov.b64 %0, {ah, bl};\n\t}"
        : "=l"(r) : "l"(a), "l"(b));
    return r;
}
__device__ __forceinline__ u64 add2(u64 a, u64 b) {
    u64 d; asm("add.rn.f32x2 %0, %1, %2;" : "=l"(d) : "l"(a), "l"(b)); return d;
}
__device__ __forceinline__ u64 mul2(u64 a, u64 b) {
    u64 d; asm("mul.rn.f32x2 %0, %1, %2;" : "=l"(d) : "l"(a), "l"(b)); return d;
}
__device__ __forceinline__ u64 fma2(u64 a, u64 b, u64 c) {
    u64 d; asm("fma.rn.f32x2 %0, %1, %2, %3;" : "=l"(d) : "l"(a), "l"(b), "l"(c)); return d;
}
__device__ __forceinline__ u64 neg2(u64 a) { return a ^ 0x8000000080000000ULL; }

// ---- fp16x2 helpers ----
__device__ __forceinline__ u64 h2f(u32 h) {
    float lo, hi;
    asm("{\n\t.reg .b16 l, h;\n\tmov.b32 {l, h}, %2;\n\t"
        "cvt.f32.f16 %0, l;\n\tcvt.f32.f16 %1, h;\n\t}"
        : "=f"(lo), "=f"(hi) : "r"(h));
    return pk2(lo, hi);
}
__device__ __forceinline__ u32 fpair2h(float lo, float hi) {
    u32 d; asm("cvt.rn.f16x2.f32 %0, %1, %2;" : "=r"(d) : "f"(hi), "f"(lo)); return d;
}
__device__ __forceinline__ u32 f2h(u64 v) {
    float lo, hi; unpk2(v, lo, hi); return fpair2h(lo, hi);
}

struct SC { u64 DTK2, ONE2, C3, C5, C2, C4; };

__global__ void __launch_bounds__(1024) flag_kernel(const float* __restrict__ om) {
    const float4* om4 = (const float4*)om;
    int acc = 0;
    for (int i = threadIdx.x; i < HW / 4; i += 1024) {
        float4 v = om4[i];
        acc |= (v.x != 0.f) | (v.y != 0.f) | (v.z != 0.f) | (v.w != 0.f);
    }
    int any = __syncthreads_or(acc);
    if (threadIdx.x == 0) g_flag = any;
}

// One fused step. State lives in caller registers; p holds the fp16 copy of
// the CURRENT state (for neighbor reads); non-final steps publish the new
// state to q. FINAL steps write results straight to global.
template <bool FINAL, int PHASE>
__device__ __forceinline__ void do_step(
    const uint2* __restrict__ p, uint2* __restrict__ q,
    u64 (&sE)[PACKS_PER], u64 (&cE)[PACKS_PER],
    u64 (&sO)[PACKS_PER], u64 (&cO)[PACKS_PER],
    int r0p, int iE, int iO, int iL, int iR,
    const SC& C, int flg, const float2* __restrict__ om2,
    int t, int y0, int b, int xe, float* __restrict__ out)
{
    // Top boundary pack (another strip's row-pair, or zero pad) -> initial u.
    uint2 tE2 = p[(r0p - 1) * RS + iE];
    uint2 tO2 = p[(r0p - 1) * RS + iO];
    u64 uEs = add2(h2f(tE2.x), sE[0]);
    u64 uEc = add2(h2f(tE2.y), cE[0]);
    u64 uOs = add2(h2f(tO2.x), sO[0]);
    u64 uOc = add2(h2f(tO2.y), cO[0]);

    int base = r0p * RS;
#pragma unroll
    for (int j = 0; j < PACKS_PER; j++) {
        u64 nEs, nEc, nOs, nOc;
        if (j < PACKS_PER - 1) {
            nEs = sE[j + 1]; nEc = cE[j + 1];
            nOs = sO[j + 1]; nOc = cO[j + 1];
        } else {
            uint2 bE2 = p[base + RS + iE];
            uint2 bO2 = p[base + RS + iO];
            nEs = h2f(bE2.x); nEc = h2f(bE2.y);
            nOs = h2f(bO2.x); nOc = h2f(bO2.y);
        }
        uint2 lf = p[base + iL];
        uint2 rg = p[base + iR];

        u64 vEs = add2(sE[j], nEs), vEc = add2(cE[j], nEc);
        u64 vOs = add2(sO[j], nOs), vOc = add2(cO[j], nOc);

        // neighbor sums: vertical via funnel(u, v), horizontal mixed reg/smem
        u64 snE = add2(funnel(uEs, vEs), add2(h2f(lf.x), sO[j]));
        u64 cnE = add2(funnel(uEc, vEc), add2(h2f(lf.y), cO[j]));
        u64 snO = add2(funnel(uOs, vOs), add2(sE[j], h2f(rg.x)));
        u64 cnO = add2(funnel(uOc, vOc), add2(cE[j], h2f(rg.y)));

        u64 dtoE = 0, dtoO = 0;
        if (flg) {   // uniform branch; omega==0 fast path skips entirely
            const int gy0 = y0 - HALO + 2 * (r0p - 1 + j);
            const int gy1 = gy0 + 1;
            float2 o0 = (gy0 >= 0 && gy0 < HH) ? om2[gy0 * TCOLS + t] : make_float2(0.f, 0.f);
            float2 o1 = (gy1 >= 0 && gy1 < HH) ? om2[gy1 * TCOLS + t] : make_float2(0.f, 0.f);
            dtoE = pk2(DTc * o0.x, DTc * o1.x);
            dtoO = pk2(DTc * o0.y, DTc * o1.y);
        }

        // rotation, even col
        u64 mE = neg2(sE[j]);
        u64 coupE = fma2(cE[j], snE, mul2(mE, cnE));
        u64 dE = fma2(C.DTK2, coupE, dtoE);
        u64 dE2 = mul2(dE, dE);
        u64 sdE = mul2(dE, fma2(dE2, fma2(dE2, C.C5, C.C3), C.ONE2));
        u64 cdE = fma2(dE2, fma2(dE2, C.C4, C.C2), C.ONE2);
        u64 nsE = fma2(sE[j], cdE, mul2(cE[j], sdE));
        u64 ncE = fma2(cE[j], cdE, mul2(mE, sdE));
        // rotation, odd col
        u64 mO = neg2(sO[j]);
        u64 coupO = fma2(cO[j], snO, mul2(mO, cnO));
        u64 dO = fma2(C.DTK2, coupO, dtoO);
        u64 dO2 = mul2(dO, dO);
        u64 sdO = mul2(dO, fma2(dO2, fma2(dO2, C.C5, C.C3), C.ONE2));
        u64 cdO = fma2(dO2, fma2(dO2, C.C4, C.C2), C.ONE2);
        u64 nsO = fma2(sO[j], cdO, mul2(cO[j], sdO));
        u64 ncO = fma2(cO[j], cdO, mul2(mO, sdO));

        if (!FINAL) {
            q[base + iE] = make_uint2(f2h(nsE), f2h(ncE));
            q[base + iO] = make_uint2(f2h(nsO), f2h(ncO));
            sE[j] = nsE; cE[j] = ncE;
            sO[j] = nsO; cO[j] = ncO;
        } else {
            float se0, se1, ce0, ce1, so0, so1, co0, co1;
            unpk2(nsE, se0, se1); unpk2(ncE, ce0, ce1);
            unpk2(nsO, so0, so1); unpk2(ncO, co0, co1);
            const int rt0 = 2 * (r0p + j - 1);
#pragma unroll
            for (int par = 0; par < 2; par++) {
                const int rt = rt0 + par;
                if (rt >= HALO && rt < HALO + TY) {
                    const int gy = y0 + (rt - HALO);
                    if (gy < HH) {
                        float ws0 = par ? se1 : se0;
                        float ws1 = par ? so1 : so0;
                        float wc0 = par ? ce1 : ce0;
                        float wc1 = par ? co1 : co0;
                        if (PHASE == 0) {
                            *(float2*)&g_s[b * HW + gy * WW + xe] = make_float2(ws0, ws1);
                            *(float2*)&g_c[b * HW + gy * WW + xe] = make_float2(wc0, wc1);
                        } else {
                            const int pix = gy * WW + xe;
                            *(float2*)&out[(long)b * (2 * HW) + pix] = make_float2(wc0, wc1);
                            *(float2*)&out[(long)b * (2 * HW) + HW + pix] = make_float2(ws0, ws1);
                        }
                    }
                }
            }
        }

        uEs = vEs; uEc = vEc; uOs = vOs; uOc = vOc;
        base += RS;
    }
}

template <int PHASE>  // 0: x_img -> g_s/g_c ; 1: g_s/g_c -> out
__global__ void __launch_bounds__(NTHREADS, 2)
fused5_kernel(const float* __restrict__ x_img,
              const float* __restrict__ omega,
              const float* __restrict__ Kp,
              float* __restrict__ out) {
    extern __shared__ uint2 sm2[];
    uint2* bufA = sm2;
    uint2* bufB = sm2 + SMP;

    const int tid = threadIdx.x;
    const int t = tid % TCOLS;         // owns pixel cols 2t, 2t+1
    const int strip = tid / TCOLS;
    const int r0p = 1 + strip * PACKS_PER;
    const int b = blockIdx.y;
    const int y0 = blockIdx.x * TY;
    const int xe = 2 * t;
    const int flg = g_flag;
    const float2* __restrict__ om2 = (const float2*)omega;

    const float DTK = DTc * Kp[0];
    SC C;
    C.DTK2 = pk2(DTK, DTK);
    C.ONE2 = pk2(1.0f, 1.0f);
    C.C3 = pk2(-1.0f / 6.0f, -1.0f / 6.0f);
    C.C5 = pk2(8.3333333e-3f, 8.3333333e-3f);
    C.C2 = pk2(-0.5f, -0.5f);
    C.C4 = pk2(4.1666668e-2f, 4.1666668e-2f);

    const int iE = t + 1;              // own even col
    const int iO = PW2 + t + 1;        // own odd col
    const int iL = PW2 + t;            // left neighbor (odd plane)
    const int iR = t + 2;              // right neighbor (even plane)

    // Zero pad ring of both buffers.
    const uint2 Z = make_uint2(0u, 0u);
    for (int i = tid; i < RS; i += NTHREADS) {
        bufA[i] = Z; bufA[(RPP - 1) * RS + i] = Z;
        bufB[i] = Z; bufB[(RPP - 1) * RS + i] = Z;
    }
    for (int r = 1 + tid; r < RPP - 1; r += NTHREADS) {
        bufA[r * RS + 113] = Z; bufA[r * RS + 114] = Z;
        bufB[r * RS + 113] = Z; bufB[r * RS + 114] = Z;
    }

    // Init: fp32 state in registers + fp16 copy into bufA.
    u64 sE[PACKS_PER], cE[PACKS_PER], sO[PACKS_PER], cO[PACKS_PER];
#pragma unroll
    for (int j = 0; j < PACKS_PER; j++) {
        const int rp = r0p + j;
        const int gy0 = y0 - HALO + 2 * (rp - 1);
        const int gy1 = gy0 + 1;
        const bool in0 = (gy0 >= 0) && (gy0 < HH);
        const bool in1 = (gy1 >= 0) && (gy1 < HH);
        float se0 = 0.f, ce0 = 0.f, so0 = 0.f, co0 = 0.f;
        float se1 = 0.f, ce1 = 0.f, so1 = 0.f, co1 = 0.f;
        if (PHASE == 0) {
            if (in0) {
                float2 v = *(const float2*)&x_img[b * HW + gy0 * WW + xe];
                __sincosf(fmaf(2.0f * PIf, v.x, -PIf), &se0, &ce0);
                __sincosf(fmaf(2.0f * PIf, v.y, -PIf), &so0, &co0);
            }
            if (in1) {
                float2 v = *(const float2*)&x_img[b * HW + gy1 * WW + xe];
                __sincosf(fmaf(2.0f * PIf, v.x, -PIf), &se1, &ce1);
                __sincosf(fmaf(2.0f * PIf, v.y, -PIf), &so1, &co1);
            }
        } else {
            if (in0) {
                float2 vs = *(const float2*)&g_s[b * HW + gy0 * WW + xe];
                float2 vc = *(const float2*)&g_c[b * HW + gy0 * WW + xe];
                se0 = vs.x; so0 = vs.y; ce0 = vc.x; co0 = vc.y;
            }
            if (in1) {
                float2 vs = *(const float2*)&g_s[b * HW + gy1 * WW + xe];
                float2 vc = *(const float2*)&g_c[b * HW + gy1 * WW + xe];
                se1 = vs.x; so1 = vs.y; ce1 = vc.x; co1 = vc.y;
            }
        }
        sE[j] = pk2(se0, se1); cE[j] = pk2(ce0, ce1);
        sO[j] = pk2(so0, so1); cO[j] = pk2(co0, co1);
        bufA[rp * RS + iE] = make_uint2(fpair2h(se0, se1), fpair2h(ce0, ce1));
        bufA[rp * RS + iO] = make_uint2(fpair2h(so0, so1), fpair2h(co0, co1));
    }

    const uint2* p = bufA;
    uint2* q = bufB;
#pragma unroll 1
    for (int st = 0; st < HALO - 1; st++) {
        __syncthreads();
        do_step<false, PHASE>(p, q, sE, cE, sO, cO, r0p, iE, iO, iL, iR,
                              C, flg, om2, t, y0, b, xe, out);
        const uint2* tp = q;
        q = (uint2*)p;
        p = tp;
    }
    __syncthreads();
    do_step<true, PHASE>(p, q, sE, cE, sO, cO, r0p, iE, iO, iL, iR,
                         C, flg, om2, t, y0, b, xe, out);
}

extern "C" void kernel_launch(void* const* d_in, const int* in_sizes, int n_in,
                              void* d_out, int out_size) {
    const float* x_img = (const float*)d_in[0];  // (B,1,H,W)
    const float* omega = (const float*)d_in[1];  // (1,1,H,W)
    const float* Kp    = (const float*)d_in[2];  // scalar
    float* out = (float*)d_out;

    static bool configured = false;
    if (!configured) {
        cudaFuncSetAttribute(fused5_kernel<0>,
                             cudaFuncAttributeMaxDynamicSharedMemorySize, SMEM_BYTES);
        cudaFuncSetAttribute(fused5_kernel<1>,
                             cudaFuncAttributeMaxDynamicSharedMemorySize, SMEM_BYTES);
        configured = true;
    }

    flag_kernel<<<1, 1024>>>(omega);

    dim3 grid(TILES, BB);
    dim3 block(NTHREADS);
    fused5_kernel<0><<<grid, block, SMEM_BYTES>>>(x_img, omega, Kp, out);
    fused5_kernel<1><<<grid, block, SMEM_BYTES>>>(x_img, omega, Kp, out);
}

// round 10
// speedup vs baseline: 1.1258x; 1.1258x over previous
#include <cuda_runtime.h>

#define HH 224
#define WW 224
#define HW (HH * WW)
#define HW2 (HW / 2)
#define BB 256
#define NTOT (BB * HW)
#define DTc 0.15f
#define PIf 3.14159265358979f

#define TY 46                  // interior rows per tile
#define HALO 5                 // 5 fused steps per kernel
#define RR (TY + 2 * HALO)     // 56 data rows
#define RPAIRS (RR / 2)        // 28 vertical row-pair packs
#define RPP (RPAIRS + 2)       // +2 zero-pad pack rows -> 30
#define TCOLS 112              // thread-columns (each owns 2 pixel cols)
#define PW2 114                // plane width incl pads
#define RS (2 * PW2)           // row stride: E plane then O plane (228 cells)
#define TILES 5                // 5*46 = 230 >= 224
#define STRIPS 4
#define NTHREADS (TCOLS * STRIPS)    // 448; 2 CTAs/SM
#define PACKS_PER (RPAIRS / STRIPS)  // 7
#define SMP (RPP * RS)               // cells per buffer = 6840
#define SMEM_BYTES (2 * SMP * 8)     // 109440 B -> 2 CTAs/SM

typedef unsigned long long u64;
typedef unsigned int u32;

// Intermediate state between phases, fp16: per (batch, row, colpair) cell
// {s_h2 = (s_col2t, s_col2t+1), c_h2 = (c_col2t, c_col2t+1)}.
__device__ uint2 g_state[(long)BB * HW2];
__device__ int g_parts[16];     // partial omega-nonzero flags

// ---- packed f32x2 helpers ----
__device__ __forceinline__ u64 pk2(float lo, float hi) {
    u64 r; asm("mov.b64 %0, {%1, %2};" : "=l"(r) : "f"(lo), "f"(hi)); return r;
}
__device__ __forceinline__ void unpk2(u64 v, float& lo, float& hi) {
    asm("mov.b64 {%0, %1}, %2;" : "=f"(lo), "=f"(hi) : "l"(v));
}
__device__ __forceinline__ u64 add2(u64 a, u64 b) {
    u64 d; asm("add.rn.f32x2 %0, %1, %2;" : "=l"(d) : "l"(a), "l"(b)); return d;
}
__device__ __forceinline__ u64 mul2(u64 a, u64 b) {
    u64 d; asm("mul.rn.f32x2 %0, %1, %2;" : "=l"(d) : "l"(a), "l"(b)); return d;
}
__device__ __forceinline__ u64 fma2(u64 a, u64 b, u64 c) {
    u64 d; asm("fma.rn.f32x2 %0, %1, %2, %3;" : "=l"(d) : "l"(a), "l"(b), "l"(c)); return d;
}
__device__ __forceinline__ u64 neg2(u64 a) { return a ^ 0x8000000080000000ULL; }

// ---- fp16x2 helpers ----
__device__ __forceinline__ u32 hadd2(u32 a, u32 b) {
    u32 d; asm("add.rn.f16x2 %0, %1, %2;" : "=r"(d) : "r"(a), "r"(b)); return d;
}
// (a.hi16, b.lo16)
__device__ __forceinline__ u32 funnel16(u32 a, u32 b) {
    u32 d; asm("prmt.b32 %0, %1, %2, 0x5432;" : "=r"(d) : "r"(a), "r"(b)); return d;
}
// (a.lo16, b.lo16)
__device__ __forceinline__ u32 los16(u32 a, u32 b) {
    u32 d; asm("prmt.b32 %0, %1, %2, 0x5410;" : "=r"(d) : "r"(a), "r"(b)); return d;
}
// (a.hi16, b.hi16)
__device__ __forceinline__ u32 his16(u32 a, u32 b) {
    u32 d; asm("prmt.b32 %0, %1, %2, 0x7632;" : "=r"(d) : "r"(a), "r"(b)); return d;
}
__device__ __forceinline__ u64 h2f(u32 h) {
    float lo, hi;
    asm("{\n\t.reg .b16 l, h;\n\tmov.b32 {l, h}, %2;\n\t"
        "cvt.f32.f16 %0, l;\n\tcvt.f32.f16 %1, h;\n\t}"
        : "=f"(lo), "=f"(hi) : "r"(h));
    return pk2(lo, hi);
}
__device__ __forceinline__ u32 fpair2h(float lo, float hi) {
    u32 d; asm("cvt.rn.f16x2.f32 %0, %1, %2;" : "=r"(d) : "f"(hi), "f"(lo)); return d;
}
__device__ __forceinline__ u32 f2h(u64 v) {
    float lo, hi; unpk2(v, lo, hi); return fpair2h(lo, hi);
}

struct SC { u64 DTK2, ONE2, C3, C5, C2, C4; };

// Rotation core: cur sin/cos fp32x2, half2 neighbor sums, dto addend.
__device__ __forceinline__ void rot_core(u64 fs, u64 fc, u32 snh, u32 cnh,
                                         u64 dto, const SC& C,
                                         u64& os, u64& oc) {
    u64 sn = h2f(snh), cn = h2f(cnh);
    u64 m = neg2(fs);
    u64 coup = fma2(fc, sn, mul2(m, cn));
    u64 d = fma2(C.DTK2, coup, dto);
    u64 d2 = mul2(d, d);
    u64 sd = mul2(d, fma2(d2, fma2(d2, C.C5, C.C3), C.ONE2));
    u64 cd = fma2(d2, fma2(d2, C.C4, C.C2), C.ONE2);
    os = fma2(fs, cd, mul2(fc, sd));
    oc = fma2(fc, cd, mul2(m, sd));
}

// 16-block partial OR of (omega != 0). Pure function of input -> deterministic.
__global__ void __launch_bounds__(1024) flag_kernel(const float* __restrict__ om) {
    const float4* om4 = (const float4*)om;
    int acc = 0;
    for (int i = blockIdx.x * 1024 + threadIdx.x; i < HW / 4; i += 16 * 1024) {
        float4 v = om4[i];
        acc |= (v.x != 0.f) | (v.y != 0.f) | (v.z != 0.f) | (v.w != 0.f);
    }
    int any = __syncthreads_or(acc);
    if (threadIdx.x == 0) g_parts[blockIdx.x] = any;
}

template <int PHASE>  // 0: x_img -> g_state ; 1: g_state -> out
__global__ void __launch_bounds__(NTHREADS, 2)
fused5_kernel(const float* __restrict__ x_img,
              const float* __restrict__ omega,
              const float* __restrict__ Kp,
              float* __restrict__ out) {
    extern __shared__ uint2 sm2[];
    uint2* bufA = sm2;
    uint2* bufB = sm2 + SMP;

    const int tid = threadIdx.x;
    const int t = tid % TCOLS;         // owns pixel cols 2t, 2t+1
    const int strip = tid / TCOLS;
    const int r0p = 1 + strip * PACKS_PER;
    const int b = blockIdx.y;
    const int y0 = blockIdx.x * TY;
    const int xe = 2 * t;
    const float2* __restrict__ om2 = (const float2*)omega;

    const float DTK = DTc * Kp[0];
    SC C;
    C.DTK2 = pk2(DTK, DTK);
    C.ONE2 = pk2(1.0f, 1.0f);
    C.C3 = pk2(-1.0f / 6.0f, -1.0f / 6.0f);
    C.C5 = pk2(8.3333333e-3f, 8.3333333e-3f);
    C.C2 = pk2(-0.5f, -0.5f);
    C.C4 = pk2(4.1666668e-2f, 4.1666668e-2f);

    const int iE = t + 1;              // own even col
    const int iO = PW2 + t + 1;        // own odd col
    const int iL = PW2 + t;            // left neighbor (odd plane)
    const int iR = t + 2;              // right neighbor (even plane)

    // Zero pad ring of both buffers (h2 zero bits = 0.0).
    const uint2 Z = make_uint2(0u, 0u);
    for (int i = tid; i < RS; i += NTHREADS) {
        bufA[i] = Z; bufA[(RPP - 1) * RS + i] = Z;
        bufB[i] = Z; bufB[(RPP - 1) * RS + i] = Z;
    }
    for (int r = 1 + tid; r < RPP - 1; r += NTHREADS) {
        bufA[r * RS + 113] = Z; bufA[r * RS + 114] = Z;
        bufB[r * RS + 113] = Z; bufB[r * RS + 114] = Z;
    }

    // Init state into bufA (fp16 cells); out-of-image rows = exact 0.
#pragma unroll
    for (int j = 0; j < PACKS_PER; j++) {
        const int rp = r0p + j;
        const int gy0 = y0 - HALO + 2 * (rp - 1);
        const int gy1 = gy0 + 1;
        const bool in0 = (gy0 >= 0) && (gy0 < HH);
        const bool in1 = (gy1 >= 0) && (gy1 < HH);
        if (PHASE == 0) {
            float sE0 = 0.f, cE0 = 0.f, sO0 = 0.f, cO0 = 0.f;
            float sE1 = 0.f, cE1 = 0.f, sO1 = 0.f, cO1 = 0.f;
            if (in0) {
                float2 v = *(const float2*)&x_img[b * HW + gy0 * WW + xe];
                __sincosf(fmaf(2.0f * PIf, v.x, -PIf), &sE0, &cE0);
                __sincosf(fmaf(2.0f * PIf, v.y, -PIf), &sO0, &cO0);
            }
            if (in1) {
                float2 v = *(const float2*)&x_img[b * HW + gy1 * WW + xe];
                __sincosf(fmaf(2.0f * PIf, v.x, -PIf), &sE1, &cE1);
                __sincosf(fmaf(2.0f * PIf, v.y, -PIf), &sO1, &cO1);
            }
            bufA[rp * RS + iE] = make_uint2(fpair2h(sE0, sE1), fpair2h(cE0, cE1));
            bufA[rp * RS + iO] = make_uint2(fpair2h(sO0, sO1), fpair2h(cO0, cO1));
        } else {
            // fp16 in, fp16 cells out: pure PRMT repack, zero conversions.
            uint2 v0 = in0 ? g_state[(long)b * HW2 + gy0 * TCOLS + t] : Z;
            uint2 v1 = in1 ? g_state[(long)b * HW2 + gy1 * TCOLS + t] : Z;
            bufA[rp * RS + iE] = make_uint2(los16(v0.x, v1.x), los16(v0.y, v1.y));
            bufA[rp * RS + iO] = make_uint2(his16(v0.x, v1.x), his16(v0.y, v1.y));
        }
    }

    // Fold the omega flag (doubles as the post-init barrier).
    int pf = (tid < 16) ? g_parts[tid] : 0;
    const int flg = __syncthreads_or(pf);

    const int gybase = y0 - HALO + 2 * (r0p - 1);
    const uint2* p = bufA;
    uint2* q = bufB;

    // Steps 1..HALO-1: smem -> smem (fp16).
#pragma unroll 1
    for (int st = 0; st < HALO - 1; st++) {
        int base = r0p * RS;
        uint2 pE = p[base - RS + iE], pO = p[base - RS + iO];
        uint2 cE = p[base + iE], cO = p[base + iO];
        u32 uEs = hadd2(pE.x, cE.x), uEc = hadd2(pE.y, cE.y);
        u32 uOs = hadd2(pO.x, cO.x), uOc = hadd2(pO.y, cO.y);
        u64 fEs = h2f(cE.x), fEc = h2f(cE.y);
        u64 fOs = h2f(cO.x), fOc = h2f(cO.y);
#pragma unroll
        for (int j = 0; j < PACKS_PER; j++) {
            uint2 nE = p[base + RS + iE];
            uint2 nO = p[base + RS + iO];
            uint2 lf = p[base + iL];
            uint2 rg = p[base + iR];

            u32 vEs = hadd2(cE.x, nE.x), vEc = hadd2(cE.y, nE.y);
            u32 vOs = hadd2(cO.x, nO.x), vOc = hadd2(cO.y, nO.y);
            u32 snE = hadd2(funnel16(uEs, vEs), hadd2(lf.x, cO.x));
            u32 cnE = hadd2(funnel16(uEc, vEc), hadd2(lf.y, cO.y));
            u32 snO = hadd2(funnel16(uOs, vOs), hadd2(cE.x, rg.x));
            u32 cnO = hadd2(funnel16(uOc, vOc), hadd2(cE.y, rg.y));

            u64 dtoE = 0, dtoO = 0;
            if (flg) {   // uniform branch; omega==0 fast path skips
                const int gy0 = gybase + 2 * j, gy1 = gy0 + 1;
                float2 o0 = (gy0 >= 0 && gy0 < HH) ? om2[gy0 * TCOLS + t] : make_float2(0.f, 0.f);
                float2 o1 = (gy1 >= 0 && gy1 < HH) ? om2[gy1 * TCOLS + t] : make_float2(0.f, 0.f);
                dtoE = pk2(DTc * o0.x, DTc * o1.x);
                dtoO = pk2(DTc * o0.y, DTc * o1.y);
            }

            u64 os, oc;
            rot_core(fEs, fEc, snE, cnE, dtoE, C, os, oc);
            q[base + iE] = make_uint2(f2h(os), f2h(oc));
            rot_core(fOs, fOc, snO, cnO, dtoO, C, os, oc);
            q[base + iO] = make_uint2(f2h(os), f2h(oc));

            uEs = vEs; uEc = vEc; uOs = vOs; uOc = vOc;
            cE = nE; cO = nO;
            fEs = h2f(nE.x); fEc = h2f(nE.y);
            fOs = h2f(nO.x); fOc = h2f(nO.y);
            base += RS;
        }
        __syncthreads();
        const uint2* tp = q;
        q = (uint2*)p;
        p = tp;
    }

    // Final step: compute fp32, write interior rows straight to global.
    {
        int base = r0p * RS;
        uint2 pE = p[base - RS + iE], pO = p[base - RS + iO];
        uint2 cE = p[base + iE], cO = p[base + iO];
        u32 uEs = hadd2(pE.x, cE.x), uEc = hadd2(pE.y, cE.y);
        u32 uOs = hadd2(pO.x, cO.x), uOc = hadd2(pO.y, cO.y);
        u64 fEs = h2f(cE.x), fEc = h2f(cE.y);
        u64 fOs = h2f(cO.x), fOc = h2f(cO.y);
#pragma unroll
        for (int j = 0; j < PACKS_PER; j++) {
            uint2 nE = p[base + RS + iE];
            uint2 nO = p[base + RS + iO];
            uint2 lf = p[base + iL];
            uint2 rg = p[base + iR];

            u32 vEs = hadd2(cE.x, nE.x), vEc = hadd2(cE.y, nE.y);
            u32 vOs = hadd2(cO.x, nO.x), vOc = hadd2(cO.y, nO.y);
            u32 snE = hadd2(funnel16(uEs, vEs), hadd2(lf.x, cO.x));
            u32 cnE = hadd2(funnel16(uEc, vEc), hadd2(lf.y, cO.y));
            u32 snO = hadd2(funnel16(uOs, vOs), hadd2(cE.x, rg.x));
            u32 cnO = hadd2(funnel16(uOc, vOc), hadd2(cE.y, rg.y));

            u64 dtoE = 0, dtoO = 0;
            if (flg) {
                const int gy0 = gybase + 2 * j, gy1 = gy0 + 1;
                float2 o0 = (gy0 >= 0 && gy0 < HH) ? om2[gy0 * TCOLS + t] : make_float2(0.f, 0.f);
                float2 o1 = (gy1 >= 0 && gy1 < HH) ? om2[gy1 * TCOLS + t] : make_float2(0.f, 0.f);
                dtoE = pk2(DTc * o0.x, DTc * o1.x);
                dtoO = pk2(DTc * o0.y, DTc * o1.y);
            }

            u64 osE, ocE, osO, ocO;
            rot_core(fEs, fEc, snE, cnE, dtoE, C, osE, ocE);
            rot_core(fOs, fOc, snO, cnO, dtoO, C, osO, ocO);

            float se0, se1, ce0, ce1, so0, so1, co0, co1;
            unpk2(osE, se0, se1); unpk2(ocE, ce0, ce1);
            unpk2(osO, so0, so1); unpk2(ocO, co0, co1);
            const int rt0 = 2 * (r0p + j - 1);
#pragma unroll
            for (int par = 0; par < 2; par++) {
                const int rt = rt0 + par;
                if (rt >= HALO && rt < HALO + TY) {
                    const int gy = y0 + (rt - HALO);
                    if (gy < HH) {
                        float ws0 = par ? se1 : se0;   // s col 2t
                        float ws1 = par ? so1 : so0;   // s col 2t+1
                        float wc0 = par ? ce1 : ce0;   // c col 2t
                        float wc1 = par ? co1 : co0;   // c col 2t+1
                        if (PHASE == 0) {
                            g_state[(long)b * HW2 + gy * TCOLS + t] =
                                make_uint2(fpair2h(ws0, ws1), fpair2h(wc0, wc1));
                        } else {
                            const int pix = gy * WW + xe;
                            *(float2*)&out[(long)b * (2 * HW) + pix] = make_float2(wc0, wc1);
                            *(float2*)&out[(long)b * (2 * HW) + HW + pix] = make_float2(ws0, ws1);
                        }
                    }
                }
            }

            uEs = vEs; uEc = vEc; uOs = vOs; uOc = vOc;
            cE = nE; cO = nO;
            fEs = h2f(nE.x); fEc = h2f(nE.y);
            fOs = h2f(nO.x); fOc = h2f(nO.y);
            base += RS;
        }
    }
}

extern "C" void kernel_launch(void* const* d_in, const int* in_sizes, int n_in,
                              void* d_out, int out_size) {
    const float* x_img = (const float*)d_in[0];  // (B,1,H,W)
    const float* omega = (const float*)d_in[1];  // (1,1,H,W)
    const float* Kp    = (const float*)d_in[2];  // scalar
    float* out = (float*)d_out;

    static bool configured = false;
    if (!configured) {
        cudaFuncSetAttribute(fused5_kernel<0>,
                             cudaFuncAttributeMaxDynamicSharedMemorySize, SMEM_BYTES);
        cudaFuncSetAttribute(fused5_kernel<1>,
                             cudaFuncAttributeMaxDynamicSharedMemorySize, SMEM_BYTES);
        configured = true;
    }

    flag_kernel<<<16, 1024>>>(omega);

    dim3 grid(TILES, BB);
    dim3 block(NTHREADS);
    fused5_kernel<0><<<grid, block, SMEM_BYTES>>>(x_img, omega, Kp, out);
    fused5_kernel<1><<<grid, block, SMEM_BYTES>>>(x_img, omega, Kp, out);
}

// round 11
// speedup vs baseline: 1.1705x; 1.0397x over previous
#include <cuda_runtime.h>

#define HH 224
#define WW 224
#define HW (HH * WW)
#define HW2 (HW / 2)
#define BB 256
#define NTOT (BB * HW)
#define DTc 0.15f
#define PIf 3.14159265358979f

#define TY 46                  // interior rows per tile
#define HALO 5                 // 5 fused steps per kernel
#define RR (TY + 2 * HALO)     // 56 data rows
#define RPAIRS (RR / 2)        // 28 vertical row-pair packs
#define RPP (RPAIRS + 2)       // +2 zero-pad pack rows -> 30
#define TCOLS 112              // thread-columns (each owns 2 pixel cols)
#define PW2 114                // plane width incl pads
#define RS (2 * PW2)           // row stride: E plane then O plane (228 cells)
#define TILES 5                // 5*46 = 230 >= 224
#define STRIPS 4
#define NTHREADS (TCOLS * STRIPS)    // 448; 2 CTAs/SM
#define PACKS_PER (RPAIRS / STRIPS)  // 7
#define SMP (RPP * RS)               // cells per buffer = 6840
#define SMEM_BYTES (2 * SMP * 8)     // 109440 B -> 2 CTAs/SM

typedef unsigned long long u64;
typedef unsigned int u32;

// Intermediate state between phases, fp16: per (batch, row, colpair) cell
// {s_h2 = (s_col2t, s_col2t+1), c_h2 = (c_col2t, c_col2t+1)}.
__device__ uint2 g_state[(long)BB * HW2];
__device__ int g_parts[64];     // partial omega-nonzero flags

// ---- packed f32x2 helpers ----
__device__ __forceinline__ u64 pk2(float lo, float hi) {
    u64 r; asm("mov.b64 %0, {%1, %2};" : "=l"(r) : "f"(lo), "f"(hi)); return r;
}
__device__ __forceinline__ void unpk2(u64 v, float& lo, float& hi) {
    asm("mov.b64 {%0, %1}, %2;" : "=f"(lo), "=f"(hi) : "l"(v));
}
__device__ __forceinline__ u64 add2(u64 a, u64 b) {
    u64 d; asm("add.rn.f32x2 %0, %1, %2;" : "=l"(d) : "l"(a), "l"(b)); return d;
}
__device__ __forceinline__ u64 mul2(u64 a, u64 b) {
    u64 d; asm("mul.rn.f32x2 %0, %1, %2;" : "=l"(d) : "l"(a), "l"(b)); return d;
}
__device__ __forceinline__ u64 fma2(u64 a, u64 b, u64 c) {
    u64 d; asm("fma.rn.f32x2 %0, %1, %2, %3;" : "=l"(d) : "l"(a), "l"(b), "l"(c)); return d;
}
__device__ __forceinline__ u64 neg2(u64 a) { return a ^ 0x8000000080000000ULL; }

// ---- fp16x2 helpers ----
__device__ __forceinline__ u32 hadd2(u32 a, u32 b) {
    u32 d; asm("add.rn.f16x2 %0, %1, %2;" : "=r"(d) : "r"(a), "r"(b)); return d;
}
// (a.hi16, b.lo16)
__device__ __forceinline__ u32 funnel16(u32 a, u32 b) {
    u32 d; asm("prmt.b32 %0, %1, %2, 0x5432;" : "=r"(d) : "r"(a), "r"(b)); return d;
}
// (a.lo16, b.lo16)
__device__ __forceinline__ u32 los16(u32 a, u32 b) {
    u32 d; asm("prmt.b32 %0, %1, %2, 0x5410;" : "=r"(d) : "r"(a), "r"(b)); return d;
}
// (a.hi16, b.hi16)
__device__ __forceinline__ u32 his16(u32 a, u32 b) {
    u32 d; asm("prmt.b32 %0, %1, %2, 0x7632;" : "=r"(d) : "r"(a), "r"(b)); return d;
}
__device__ __forceinline__ u64 h2f(u32 h) {
    float lo, hi;
    asm("{\n\t.reg .b16 l, h;\n\tmov.b32 {l, h}, %2;\n\t"
        "cvt.f32.f16 %0, l;\n\tcvt.f32.f16 %1, h;\n\t}"
        : "=f"(lo), "=f"(hi) : "r"(h));
    return pk2(lo, hi);
}
__device__ __forceinline__ u32 fpair2h(float lo, float hi) {
    u32 d; asm("cvt.rn.f16x2.f32 %0, %1, %2;" : "=r"(d) : "f"(hi), "f"(lo)); return d;
}
__device__ __forceinline__ u32 f2h(u64 v) {
    float lo, hi; unpk2(v, lo, hi); return fpair2h(lo, hi);
}

struct SC { u64 DTK2, ONE2, C3, C2, C4; };

// Rotation core: cur sin/cos fp32x2, half2 neighbor sums, dto addend.
// |d| <= 0.3: sd = d(1 - d^2/6) (d^5 term <= 2e-5 absolute, dropped),
//             cd = 1 - d^2/2 + d^4/24.
__device__ __forceinline__ void rot_core(u64 fs, u64 fc, u32 snh, u32 cnh,
                                         u64 dto, const SC& C,
                                         u64& os, u64& oc) {
    u64 sn = h2f(snh), cn = h2f(cnh);
    u64 m = neg2(fs);
    u64 coup = fma2(fc, sn, mul2(m, cn));
    u64 d = fma2(C.DTK2, coup, dto);
    u64 d2 = mul2(d, d);
    u64 sd = mul2(d, fma2(d2, C.C3, C.ONE2));
    u64 cd = fma2(d2, fma2(d2, C.C4, C.C2), C.ONE2);
    os = fma2(fs, cd, mul2(fc, sd));
    oc = fma2(fc, cd, mul2(m, sd));
}

// 64-block partial OR of (omega != 0). Pure function of input -> deterministic.
__global__ void __launch_bounds__(256) flag_kernel(const float* __restrict__ om) {
    const float4* om4 = (const float4*)om;
    int acc = 0;
    for (int i = blockIdx.x * 256 + threadIdx.x; i < HW / 4; i += 64 * 256) {
        float4 v = om4[i];
        acc |= (v.x != 0.f) | (v.y != 0.f) | (v.z != 0.f) | (v.w != 0.f);
    }
    int any = __syncthreads_or(acc);
    if (threadIdx.x == 0) g_parts[blockIdx.x] = any;
}

template <int PHASE>  // 0: x_img -> g_state ; 1: g_state -> out
__global__ void __launch_bounds__(NTHREADS, 2)
fused5_kernel(const float* __restrict__ x_img,
              const float* __restrict__ omega,
              const float* __restrict__ Kp,
              float* __restrict__ out) {
    extern __shared__ uint2 sm2[];
    uint2* bufA = sm2;
    uint2* bufB = sm2 + SMP;

    const int tid = threadIdx.x;
    const int t = tid % TCOLS;         // owns pixel cols 2t, 2t+1
    const int strip = tid / TCOLS;
    const int r0p = 1 + strip * PACKS_PER;
    const int b = blockIdx.y;
    const int y0 = blockIdx.x * TY;
    const int xe = 2 * t;
    const float2* __restrict__ om2 = (const float2*)omega;

    const float DTK = DTc * Kp[0];
    SC C;
    C.DTK2 = pk2(DTK, DTK);
    C.ONE2 = pk2(1.0f, 1.0f);
    C.C3 = pk2(-1.0f / 6.0f, -1.0f / 6.0f);
    C.C2 = pk2(-0.5f, -0.5f);
    C.C4 = pk2(4.1666668e-2f, 4.1666668e-2f);

    const int iE = t + 1;              // own even col
    const int iO = PW2 + t + 1;        // own odd col
    const int iL = PW2 + t;            // left neighbor (odd plane)
    const int iR = t + 2;              // right neighbor (even plane)

    // Zero pad ring of both buffers (h2 zero bits = 0.0).
    const uint2 Z = make_uint2(0u, 0u);
    for (int i = tid; i < RS; i += NTHREADS) {
        bufA[i] = Z; bufA[(RPP - 1) * RS + i] = Z;
        bufB[i] = Z; bufB[(RPP - 1) * RS + i] = Z;
    }
    for (int r = 1 + tid; r < RPP - 1; r += NTHREADS) {
        bufA[r * RS + 113] = Z; bufA[r * RS + 114] = Z;
        bufB[r * RS + 113] = Z; bufB[r * RS + 114] = Z;
    }

    // Init state into bufA (fp16 cells); out-of-image rows = exact 0.
#pragma unroll
    for (int j = 0; j < PACKS_PER; j++) {
        const int rp = r0p + j;
        const int gy0 = y0 - HALO + 2 * (rp - 1);
        const int gy1 = gy0 + 1;
        const bool in0 = (gy0 >= 0) && (gy0 < HH);
        const bool in1 = (gy1 >= 0) && (gy1 < HH);
        if (PHASE == 0) {
            float sE0 = 0.f, cE0 = 0.f, sO0 = 0.f, cO0 = 0.f;
            float sE1 = 0.f, cE1 = 0.f, sO1 = 0.f, cO1 = 0.f;
            if (in0) {
                float2 v = *(const float2*)&x_img[b * HW + gy0 * WW + xe];
                __sincosf(fmaf(2.0f * PIf, v.x, -PIf), &sE0, &cE0);
                __sincosf(fmaf(2.0f * PIf, v.y, -PIf), &sO0, &cO0);
            }
            if (in1) {
                float2 v = *(const float2*)&x_img[b * HW + gy1 * WW + xe];
                __sincosf(fmaf(2.0f * PIf, v.x, -PIf), &sE1, &cE1);
                __sincosf(fmaf(2.0f * PIf, v.y, -PIf), &sO1, &cO1);
            }
            bufA[rp * RS + iE] = make_uint2(fpair2h(sE0, sE1), fpair2h(cE0, cE1));
            bufA[rp * RS + iO] = make_uint2(fpair2h(sO0, sO1), fpair2h(cO0, cO1));
        } else {
            // fp16 in, fp16 cells out: pure PRMT repack, zero conversions.
            uint2 v0 = in0 ? g_state[(long)b * HW2 + gy0 * TCOLS + t] : Z;
            uint2 v1 = in1 ? g_state[(long)b * HW2 + gy1 * TCOLS + t] : Z;
            bufA[rp * RS + iE] = make_uint2(los16(v0.x, v1.x), los16(v0.y, v1.y));
            bufA[rp * RS + iO] = make_uint2(his16(v0.x, v1.x), his16(v0.y, v1.y));
        }
    }

    // Fold the omega flag (doubles as the post-init barrier).
    int pf = (tid < 64) ? g_parts[tid] : 0;
    const int flg = __syncthreads_or(pf);

    const int gybase = y0 - HALO + 2 * (r0p - 1);
    const uint2* p = bufA;
    uint2* q = bufB;

    // Steps 1..HALO-1: smem -> smem (fp16), software-pipelined loads.
#pragma unroll 1
    for (int st = 0; st < HALO - 1; st++) {
        int base = r0p * RS;
        uint2 pE = p[base - RS + iE], pO = p[base - RS + iO];
        uint2 cE = p[base + iE], cO = p[base + iO];
        u32 uEs = hadd2(pE.x, cE.x), uEc = hadd2(pE.y, cE.y);
        u32 uOs = hadd2(pO.x, cO.x), uOc = hadd2(pO.y, cO.y);
        u64 fEs = h2f(cE.x), fEc = h2f(cE.y);
        u64 fOs = h2f(cO.x), fOc = h2f(cO.y);
        // Prologue loads for iter 0.
        uint2 nE = p[base + RS + iE];
        uint2 nO = p[base + RS + iO];
        uint2 lf = p[base + iL];
        uint2 rg = p[base + iR];
#pragma unroll
        for (int j = 0; j < PACKS_PER; j++) {
            // Prefetch next iteration's loads ahead of this iteration's compute.
            uint2 nE2, nO2, lf2, rg2;
            if (j < PACKS_PER - 1) {
                nE2 = p[base + 2 * RS + iE];
                nO2 = p[base + 2 * RS + iO];
                lf2 = p[base + RS + iL];
                rg2 = p[base + RS + iR];
            }

            u32 vEs = hadd2(cE.x, nE.x), vEc = hadd2(cE.y, nE.y);
            u32 vOs = hadd2(cO.x, nO.x), vOc = hadd2(cO.y, nO.y);
            u32 snE = hadd2(funnel16(uEs, vEs), hadd2(lf.x, cO.x));
            u32 cnE = hadd2(funnel16(uEc, vEc), hadd2(lf.y, cO.y));
            u32 snO = hadd2(funnel16(uOs, vOs), hadd2(cE.x, rg.x));
            u32 cnO = hadd2(funnel16(uOc, vOc), hadd2(cE.y, rg.y));

            u64 dtoE = 0, dtoO = 0;
            if (flg) {   // uniform branch; omega==0 fast path skips
                const int gy0 = gybase + 2 * j, gy1 = gy0 + 1;
                float2 o0 = (gy0 >= 0 && gy0 < HH) ? om2[gy0 * TCOLS + t] : make_float2(0.f, 0.f);
                float2 o1 = (gy1 >= 0 && gy1 < HH) ? om2[gy1 * TCOLS + t] : make_float2(0.f, 0.f);
                dtoE = pk2(DTc * o0.x, DTc * o1.x);
                dtoO = pk2(DTc * o0.y, DTc * o1.y);
            }

            u64 os, oc;
            rot_core(fEs, fEc, snE, cnE, dtoE, C, os, oc);
            q[base + iE] = make_uint2(f2h(os), f2h(oc));
            rot_core(fOs, fOc, snO, cnO, dtoO, C, os, oc);
            q[base + iO] = make_uint2(f2h(os), f2h(oc));

            uEs = vEs; uEc = vEc; uOs = vOs; uOc = vOc;
            cE = nE; cO = nO;
            fEs = h2f(nE.x); fEc = h2f(nE.y);
            fOs = h2f(nO.x); fOc = h2f(nO.y);
            nE = nE2; nO = nO2; lf = lf2; rg = rg2;
            base += RS;
        }
        __syncthreads();
        const uint2* tp = q;
        q = (uint2*)p;
        p = tp;
    }

    // Final step: compute fp32, write interior rows straight to global.
    {
        int base = r0p * RS;
        uint2 pE = p[base - RS + iE], pO = p[base - RS + iO];
        uint2 cE = p[base + iE], cO = p[base + iO];
        u32 uEs = hadd2(pE.x, cE.x), uEc = hadd2(pE.y, cE.y);
        u32 uOs = hadd2(pO.x, cO.x), uOc = hadd2(pO.y, cO.y);
        u64 fEs = h2f(cE.x), fEc = h2f(cE.y);
        u64 fOs = h2f(cO.x), fOc = h2f(cO.y);
        uint2 nE = p[base + RS + iE];
        uint2 nO = p[base + RS + iO];
        uint2 lf = p[base + iL];
        uint2 rg = p[base + iR];
#pragma unroll
        for (int j = 0; j < PACKS_PER; j++) {
            uint2 nE2, nO2, lf2, rg2;
            if (j < PACKS_PER - 1) {
                nE2 = p[base + 2 * RS + iE];
                nO2 = p[base + 2 * RS + iO];
                lf2 = p[base + RS + iL];
                rg2 = p[base + RS + iR];
            }

            u32 vEs = hadd2(cE.x, nE.x), vEc = hadd2(cE.y, nE.y);
            u32 vOs = hadd2(cO.x, nO.x), vOc = hadd2(cO.y, nO.y);
            u32 snE = hadd2(funnel16(uEs, vEs), hadd2(lf.x, cO.x));
            u32 cnE = hadd2(funnel16(uEc, vEc), hadd2(lf.y, cO.y));
            u32 snO = hadd2(funnel16(uOs, vOs), hadd2(cE.x, rg.x));
            u32 cnO = hadd2(funnel16(uOc, vOc), hadd2(cE.y, rg.y));

            u64 dtoE = 0, dtoO = 0;
            if (flg) {
                const int gy0 = gybase + 2 * j, gy1 = gy0 + 1;
                float2 o0 = (gy0 >= 0 && gy0 < HH) ? om2[gy0 * TCOLS + t] : make_float2(0.f, 0.f);
                float2 o1 = (gy1 >= 0 && gy1 < HH) ? om2[gy1 * TCOLS + t] : make_float2(0.f, 0.f);
                dtoE = pk2(DTc * o0.x, DTc * o1.x);
                dtoO = pk2(DTc * o0.y, DTc * o1.y);
            }

            u64 osE, ocE, osO, ocO;
            rot_core(fEs, fEc, snE, cnE, dtoE, C, osE, ocE);
            rot_core(fOs, fOc, snO, cnO, dtoO, C, osO, ocO);

            float se0, se1, ce0, ce1, so0, so1, co0, co1;
            unpk2(osE, se0, se1); unpk2(ocE, ce0, ce1);
            unpk2(osO, so0, so1); unpk2(ocO, co0, co1);
            const int rt0 = 2 * (r0p + j - 1);
#pragma unroll
            for (int par = 0; par < 2; par++) {
                const int rt = rt0 + par;
                if (rt >= HALO && rt < HALO + TY) {
                    const int gy = y0 + (rt - HALO);
                    if (gy < HH) {
                        float ws0 = par ? se1 : se0;   // s col 2t
                        float ws1 = par ? so1 : so0;   // s col 2t+1
                        float wc0 = par ? ce1 : ce0;   // c col 2t
                        float wc1 = par ? co1 : co0;   // c col 2t+1
                        if (PHASE == 0) {
                            g_state[(long)b * HW2 + gy * TCOLS + t] =
                                make_uint2(fpair2h(ws0, ws1), fpair2h(wc0, wc1));
                        } else {
                            const int pix = gy * WW + xe;
                            *(float2*)&out[(long)b * (2 * HW) + pix] = make_float2(wc0, wc1);
                            *(float2*)&out[(long)b * (2 * HW) + HW + pix] = make_float2(ws0, ws1);
                        }
                    }
                }
            }

            uEs = vEs; uEc = vEc; uOs = vOs; uOc = vOc;
            cE = nE; cO = nO;
            fEs = h2f(nE.x); fEc = h2f(nE.y);
            fOs = h2f(nO.x); fOc = h2f(nO.y);
            nE = nE2; nO = nO2; lf = lf2; rg = rg2;
            base += RS;
        }
    }
}

extern "C" void kernel_launch(void* const* d_in, const int* in_sizes, int n_in,
                              void* d_out, int out_size) {
    const float* x_img = (const float*)d_in[0];  // (B,1,H,W)
    const float* omega = (const float*)d_in[1];  // (1,1,H,W)
    const float* Kp    = (const float*)d_in[2];  // scalar
    float* out = (float*)d_out;

    static bool configured = false;
    if (!configured) {
        cudaFuncSetAttribute(fused5_kernel<0>,
                             cudaFuncAttributeMaxDynamicSharedMemorySize, SMEM_BYTES);
        cudaFuncSetAttribute(fused5_kernel<1>,
                             cudaFuncAttributeMaxDynamicSharedMemorySize, SMEM_BYTES);
        configured = true;
    }

    flag_kernel<<<64, 256>>>(omega);

    dim3 grid(TILES, BB);
    dim3 block(NTHREADS);
    fused5_kernel<0><<<grid, block, SMEM_BYTES>>>(x_img, omega, Kp, out);
    fused5_kernel<1><<<grid, block, SMEM_BYTES>>>(x_img, omega, Kp, out);
}

// round 12
// speedup vs baseline: 1.1748x; 1.0037x over previous
#include <cuda_runtime.h>

#define HH 224
#define WW 224
#define HW (HH * WW)
#define HW2 (HW / 2)
#define BB 256
#define NTOT (BB * HW)
#define DTc 0.15f
#define PIf 3.14159265358979f

#define TY 46                  // interior rows per tile
#define HALO 5                 // 5 fused steps per kernel
#define RR (TY + 2 * HALO)     // 56 data rows
#define RPAIRS (RR / 2)        // 28 vertical row-pair packs
#define RPP (RPAIRS + 2)       // +2 zero-pad pack rows -> 30
#define TCOLS 112              // thread-columns (each owns 2 pixel cols)
#define CW 114                 // cells per pack row incl 2 pads
#define TILES 5                // 5*46 = 230 >= 224
#define STRIPS 4
#define NTHREADS (TCOLS * STRIPS)    // 448; 2 CTAs/SM
#define PACKS_PER (RPAIRS / STRIPS)  // 7
#define SMP (RPP * CW)               // uint4 cells per buffer = 3420
#define SMEM_BYTES (2 * SMP * 16)    // 109440 B -> 2 CTAs/SM

typedef unsigned long long u64;
typedef unsigned int u32;

// Intermediate state between phases, fp16: per (batch, row, colpair) cell
// {s_h2 = (s_col2t, s_col2t+1), c_h2 = (c_col2t, c_col2t+1)}.
__device__ uint2 g_state[(long)BB * HW2];
__device__ int g_parts[64];     // partial omega-nonzero flags

// ---- packed f32x2 helpers ----
__device__ __forceinline__ u64 pk2(float lo, float hi) {
    u64 r; asm("mov.b64 %0, {%1, %2};" : "=l"(r) : "f"(lo), "f"(hi)); return r;
}
__device__ __forceinline__ void unpk2(u64 v, float& lo, float& hi) {
    asm("mov.b64 {%0, %1}, %2;" : "=f"(lo), "=f"(hi) : "l"(v));
}
__device__ __forceinline__ u64 mul2(u64 a, u64 b) {
    u64 d; asm("mul.rn.f32x2 %0, %1, %2;" : "=l"(d) : "l"(a), "l"(b)); return d;
}
__device__ __forceinline__ u64 fma2(u64 a, u64 b, u64 c) {
    u64 d; asm("fma.rn.f32x2 %0, %1, %2, %3;" : "=l"(d) : "l"(a), "l"(b), "l"(c)); return d;
}
__device__ __forceinline__ u64 neg2(u64 a) { return a ^ 0x8000000080000000ULL; }

// ---- fp16x2 helpers ----
__device__ __forceinline__ u32 hadd2(u32 a, u32 b) {
    u32 d; asm("add.rn.f16x2 %0, %1, %2;" : "=r"(d) : "r"(a), "r"(b)); return d;
}
// (a.hi16, b.lo16)
__device__ __forceinline__ u32 funnel16(u32 a, u32 b) {
    u32 d; asm("prmt.b32 %0, %1, %2, 0x5432;" : "=r"(d) : "r"(a), "r"(b)); return d;
}
// (a.lo16, b.lo16)
__device__ __forceinline__ u32 los16(u32 a, u32 b) {
    u32 d; asm("prmt.b32 %0, %1, %2, 0x5410;" : "=r"(d) : "r"(a), "r"(b)); return d;
}
// (a.hi16, b.hi16)
__device__ __forceinline__ u32 his16(u32 a, u32 b) {
    u32 d; asm("prmt.b32 %0, %1, %2, 0x7632;" : "=r"(d) : "r"(a), "r"(b)); return d;
}
__device__ __forceinline__ u64 h2f(u32 h) {
    float lo, hi;
    asm("{\n\t.reg .b16 l, h;\n\tmov.b32 {l, h}, %2;\n\t"
        "cvt.f32.f16 %0, l;\n\tcvt.f32.f16 %1, h;\n\t}"
        : "=f"(lo), "=f"(hi) : "r"(h));
    return pk2(lo, hi);
}
__device__ __forceinline__ u32 fpair2h(float lo, float hi) {
    u32 d; asm("cvt.rn.f16x2.f32 %0, %1, %2;" : "=r"(d) : "f"(hi), "f"(lo)); return d;
}
__device__ __forceinline__ u32 f2h(u64 v) {
    float lo, hi; unpk2(v, lo, hi); return fpair2h(lo, hi);
}

// 8-byte half-cell shared load: half=0 -> (x,y), half=8 -> (z,w).
__device__ __forceinline__ uint2 lds8(const uint4* buf, int cellIdx, int halfBytes) {
    return *(const uint2*)((const char*)(buf + cellIdx) + halfBytes);
}

struct SC { u64 DTK2, ONE2, C3, C2, C4; };

// Rotation core: cur sin/cos fp32x2, half2 neighbor sums, dto addend.
// |d| <= 0.3: sd = d(1 - d^2/6), cd = 1 - d^2/2 + d^4/24.
__device__ __forceinline__ void rot_core(u64 fs, u64 fc, u32 snh, u32 cnh,
                                         u64 dto, const SC& C,
                                         u64& os, u64& oc) {
    u64 sn = h2f(snh), cn = h2f(cnh);
    u64 m = neg2(fs);
    u64 coup = fma2(fc, sn, mul2(m, cn));
    u64 d = fma2(C.DTK2, coup, dto);
    u64 d2 = mul2(d, d);
    u64 sd = mul2(d, fma2(d2, C.C3, C.ONE2));
    u64 cd = fma2(d2, fma2(d2, C.C4, C.C2), C.ONE2);
    os = fma2(fs, cd, mul2(fc, sd));
    oc = fma2(fc, cd, mul2(m, sd));
}

// 64-block partial OR of (omega != 0). Pure function of input -> deterministic.
__global__ void __launch_bounds__(256) flag_kernel(const float* __restrict__ om) {
    const float4* om4 = (const float4*)om;
    int acc = 0;
    for (int i = blockIdx.x * 256 + threadIdx.x; i < HW / 4; i += 64 * 256) {
        float4 v = om4[i];
        acc |= (v.x != 0.f) | (v.y != 0.f) | (v.z != 0.f) | (v.w != 0.f);
    }
    int any = __syncthreads_or(acc);
    if (threadIdx.x == 0) g_parts[blockIdx.x] = any;
}

template <int PHASE>  // 0: x_img -> g_state ; 1: g_state -> out
__global__ void __launch_bounds__(NTHREADS, 2)
fused5_kernel(const float* __restrict__ x_img,
              const float* __restrict__ omega,
              const float* __restrict__ Kp,
              float* __restrict__ out) {
    extern __shared__ uint4 sm4[];
    uint4* bufA = sm4;
    uint4* bufB = sm4 + SMP;

    const int tid = threadIdx.x;
    const int t = tid % TCOLS;         // owns pixel cols 2t, 2t+1
    const int strip = tid / TCOLS;
    const int r0p = 1 + strip * PACKS_PER;
    const int b = blockIdx.y;
    const int y0 = blockIdx.x * TY;
    const int xe = 2 * t;
    const int ic = t + 1;              // own cell within row
    const float2* __restrict__ om2 = (const float2*)omega;

    const float DTK = DTc * Kp[0];
    SC C;
    C.DTK2 = pk2(DTK, DTK);
    C.ONE2 = pk2(1.0f, 1.0f);
    C.C3 = pk2(-1.0f / 6.0f, -1.0f / 6.0f);
    C.C2 = pk2(-0.5f, -0.5f);
    C.C4 = pk2(4.1666668e-2f, 4.1666668e-2f);

    // Zero pad ring of both buffers (h2 zero bits = 0.0).
    const uint4 Z = make_uint4(0u, 0u, 0u, 0u);
    for (int i = tid; i < CW; i += NTHREADS) {
        bufA[i] = Z; bufA[(RPP - 1) * CW + i] = Z;
        bufB[i] = Z; bufB[(RPP - 1) * CW + i] = Z;
    }
    for (int r = 1 + tid; r < RPP - 1; r += NTHREADS) {
        bufA[r * CW] = Z; bufA[r * CW + CW - 1] = Z;
        bufB[r * CW] = Z; bufB[r * CW + CW - 1] = Z;
    }

    // Init state into bufA; out-of-image rows = exact 0.
#pragma unroll
    for (int j = 0; j < PACKS_PER; j++) {
        const int rp = r0p + j;
        const int gy0 = y0 - HALO + 2 * (rp - 1);
        const int gy1 = gy0 + 1;
        const bool in0 = (gy0 >= 0) && (gy0 < HH);
        const bool in1 = (gy1 >= 0) && (gy1 < HH);
        if (PHASE == 0) {
            float sE0 = 0.f, cE0 = 0.f, sO0 = 0.f, cO0 = 0.f;
            float sE1 = 0.f, cE1 = 0.f, sO1 = 0.f, cO1 = 0.f;
            if (in0) {
                float2 v = *(const float2*)&x_img[b * HW + gy0 * WW + xe];
                __sincosf(fmaf(2.0f * PIf, v.x, -PIf), &sE0, &cE0);
                __sincosf(fmaf(2.0f * PIf, v.y, -PIf), &sO0, &cO0);
            }
            if (in1) {
                float2 v = *(const float2*)&x_img[b * HW + gy1 * WW + xe];
                __sincosf(fmaf(2.0f * PIf, v.x, -PIf), &sE1, &cE1);
                __sincosf(fmaf(2.0f * PIf, v.y, -PIf), &sO1, &cO1);
            }
            bufA[rp * CW + ic] = make_uint4(fpair2h(sE0, sE1), fpair2h(cE0, cE1),
                                            fpair2h(sO0, sO1), fpair2h(cO0, cO1));
        } else {
            // fp16 in, fp16 cells out: pure PRMT repack, zero conversions.
            uint2 v0 = in0 ? g_state[(long)b * HW2 + gy0 * TCOLS + t] : make_uint2(0u, 0u);
            uint2 v1 = in1 ? g_state[(long)b * HW2 + gy1 * TCOLS + t] : make_uint2(0u, 0u);
            bufA[rp * CW + ic] = make_uint4(los16(v0.x, v1.x), los16(v0.y, v1.y),
                                            his16(v0.x, v1.x), his16(v0.y, v1.y));
        }
    }

    // Fold the omega flag (doubles as the post-init barrier).
    int pf = (tid < 64) ? g_parts[tid] : 0;
    const int flg = __syncthreads_or(pf);

    const int gybase = y0 - HALO + 2 * (r0p - 1);
    const uint4* p = bufA;
    uint4* q = bufB;

    // Steps 1..HALO-1: smem -> smem (fp16), software-pipelined loads.
#pragma unroll 1
    for (int st = 0; st < HALO - 1; st++) {
        int idx = r0p * CW + ic;
        uint4 t4 = p[idx - CW];
        uint4 c4 = p[idx];
        u32 uEs = hadd2(t4.x, c4.x), uEc = hadd2(t4.y, c4.y);
        u32 uOs = hadd2(t4.z, c4.z), uOc = hadd2(t4.w, c4.w);
        u64 fEs = h2f(c4.x), fEc = h2f(c4.y);
        u64 fOs = h2f(c4.z), fOc = h2f(c4.w);
        // Prologue loads for iter 0.
        uint4 n4 = p[idx + CW];
        uint2 lf = lds8(p, idx - 1, 8);   // left cell O-half: (sO, cO) of col 2t-1
        uint2 rg = lds8(p, idx + 1, 0);   // right cell E-half: (sE, cE) of col 2t+2
#pragma unroll
        for (int j = 0; j < PACKS_PER; j++) {
            // Prefetch next iteration's loads ahead of this iteration's compute.
            uint4 n42; uint2 lf2, rg2;
            if (j < PACKS_PER - 1) {
                n42 = p[idx + 2 * CW];
                lf2 = lds8(p, idx + CW - 1, 8);
                rg2 = lds8(p, idx + CW + 1, 0);
            }

            u32 vEs = hadd2(c4.x, n4.x), vEc = hadd2(c4.y, n4.y);
            u32 vOs = hadd2(c4.z, n4.z), vOc = hadd2(c4.w, n4.w);
            u32 snE = hadd2(funnel16(uEs, vEs), hadd2(lf.x, c4.z));
            u32 cnE = hadd2(funnel16(uEc, vEc), hadd2(lf.y, c4.w));
            u32 snO = hadd2(funnel16(uOs, vOs), hadd2(c4.x, rg.x));
            u32 cnO = hadd2(funnel16(uOc, vOc), hadd2(c4.y, rg.y));

            u64 dtoE = 0, dtoO = 0;
            if (flg) {   // uniform branch; omega==0 fast path skips
                const int gy0 = gybase + 2 * j, gy1 = gy0 + 1;
                float2 o0 = (gy0 >= 0 && gy0 < HH) ? om2[gy0 * TCOLS + t] : make_float2(0.f, 0.f);
                float2 o1 = (gy1 >= 0 && gy1 < HH) ? om2[gy1 * TCOLS + t] : make_float2(0.f, 0.f);
                dtoE = pk2(DTc * o0.x, DTc * o1.x);
                dtoO = pk2(DTc * o0.y, DTc * o1.y);
            }

            u64 osE, ocE, osO, ocO;
            rot_core(fEs, fEc, snE, cnE, dtoE, C, osE, ocE);
            rot_core(fOs, fOc, snO, cnO, dtoO, C, osO, ocO);
            q[idx] = make_uint4(f2h(osE), f2h(ocE), f2h(osO), f2h(ocO));

            uEs = vEs; uEc = vEc; uOs = vOs; uOc = vOc;
            c4 = n4;
            fEs = h2f(n4.x); fEc = h2f(n4.y);
            fOs = h2f(n4.z); fOc = h2f(n4.w);
            n4 = n42; lf = lf2; rg = rg2;
            idx += CW;
        }
        __syncthreads();
        const uint4* tp = q;
        q = (uint4*)p;
        p = tp;
    }

    // Final step: compute fp32, write interior rows straight to global.
    {
        int idx = r0p * CW + ic;
        uint4 t4 = p[idx - CW];
        uint4 c4 = p[idx];
        u32 uEs = hadd2(t4.x, c4.x), uEc = hadd2(t4.y, c4.y);
        u32 uOs = hadd2(t4.z, c4.z), uOc = hadd2(t4.w, c4.w);
        u64 fEs = h2f(c4.x), fEc = h2f(c4.y);
        u64 fOs = h2f(c4.z), fOc = h2f(c4.w);
        uint4 n4 = p[idx + CW];
        uint2 lf = lds8(p, idx - 1, 8);
        uint2 rg = lds8(p, idx + 1, 0);
#pragma unroll
        for (int j = 0; j < PACKS_PER; j++) {
            uint4 n42; uint2 lf2, rg2;
            if (j < PACKS_PER - 1) {
                n42 = p[idx + 2 * CW];
                lf2 = lds8(p, idx + CW - 1, 8);
                rg2 = lds8(p, idx + CW + 1, 0);
            }

            u32 vEs = hadd2(c4.x, n4.x), vEc = hadd2(c4.y, n4.y);
            u32 vOs = hadd2(c4.z, n4.z), vOc = hadd2(c4.w, n4.w);
            u32 snE = hadd2(funnel16(uEs, vEs), hadd2(lf.x, c4.z));
            u32 cnE = hadd2(funnel16(uEc, vEc), hadd2(lf.y, c4.w));
            u32 snO = hadd2(funnel16(uOs, vOs), hadd2(c4.x, rg.x));
            u32 cnO = hadd2(funnel16(uOc, vOc), hadd2(c4.y, rg.y));

            u64 dtoE = 0, dtoO = 0;
            if (flg) {
                const int gy0 = gybase + 2 * j, gy1 = gy0 + 1;
                float2 o0 = (gy0 >= 0 && gy0 < HH) ? om2[gy0 * TCOLS + t] : make_float2(0.f, 0.f);
                float2 o1 = (gy1 >= 0 && gy1 < HH) ? om2[gy1 * TCOLS + t] : make_float2(0.f, 0.f);
                dtoE = pk2(DTc * o0.x, DTc * o1.x);
                dtoO = pk2(DTc * o0.y, DTc * o1.y);
            }

            u64 osE, ocE, osO, ocO;
            rot_core(fEs, fEc, snE, cnE, dtoE, C, osE, ocE);
            rot_core(fOs, fOc, snO, cnO, dtoO, C, osO, ocO);

            float se0, se1, ce0, ce1, so0, so1, co0, co1;
            unpk2(osE, se0, se1); unpk2(ocE, ce0, ce1);
            unpk2(osO, so0, so1); unpk2(ocO, co0, co1);
            const int rt0 = 2 * (r0p + j - 1);
#pragma unroll
            for (int par = 0; par < 2; par++) {
                const int rt = rt0 + par;
                if (rt >= HALO && rt < HALO + TY) {
                    const int gy = y0 + (rt - HALO);
                    if (gy < HH) {
                        float ws0 = par ? se1 : se0;   // s col 2t
                        float ws1 = par ? so1 : so0;   // s col 2t+1
                        float wc0 = par ? ce1 : ce0;   // c col 2t
                        float wc1 = par ? co1 : co0;   // c col 2t+1
                        if (PHASE == 0) {
                            g_state[(long)b * HW2 + gy * TCOLS + t] =
                                make_uint2(fpair2h(ws0, ws1), fpair2h(wc0, wc1));
                        } else {
                            const int pix = gy * WW + xe;
                            *(float2*)&out[(long)b * (2 * HW) + pix] = make_float2(wc0, wc1);
                            *(float2*)&out[(long)b * (2 * HW) + HW + pix] = make_float2(ws0, ws1);
                        }
                    }
                }
            }

            uEs = vEs; uEc = vEc; uOs = vOs; uOc = vOc;
            c4 = n4;
            fEs = h2f(n4.x); fEc = h2f(n4.y);
            fOs = h2f(n4.z); fOc = h2f(n4.w);
            n4 = n42; lf = lf2; rg = rg2;
            idx += CW;
        }
    }
}

extern "C" void kernel_launch(void* const* d_in, const int* in_sizes, int n_in,
                              void* d_out, int out_size) {
    const float* x_img = (const float*)d_in[0];  // (B,1,H,W)
    const float* omega = (const float*)d_in[1];  // (1,1,H,W)
    const float* Kp    = (const float*)d_in[2];  // scalar
    float* out = (float*)d_out;

    static bool configured = false;
    if (!configured) {
        cudaFuncSetAttribute(fused5_kernel<0>,
                             cudaFuncAttributeMaxDynamicSharedMemorySize, SMEM_BYTES);
        cudaFuncSetAttribute(fused5_kernel<1>,
                             cudaFuncAttributeMaxDynamicSharedMemorySize, SMEM_BYTES);
        configured = true;
    }

    flag_kernel<<<64, 256>>>(omega);

    dim3 grid(TILES, BB);
    dim3 block(NTHREADS);
    fused5_kernel<0><<<grid, block, SMEM_BYTES>>>(x_img, omega, Kp, out);
    fused5_kernel<1><<<grid, block, SMEM_BYTES>>>(x_img, omega, Kp, out);
}